// round 13
// baseline (speedup 1.0000x reference)
#include <cuda_runtime.h>
#include <cuda_bf16.h>
#include <math.h>
#include <stdint.h>

// Problem constants: B=64, C=20, K=5, Q=15, D=H=2048
#define D_DIM 2048
#define GK    2048
#define NSUP  6400
#define NQRY  19200
#define NEP   64
#define SPE   100
#define QPE   300
#define NCLS  20

// Scratch (device globals: allocation-free per harness rules)
__device__ __nv_bfloat16 g_w_hi[GK * GK];     // W split hi  [k][n]
__device__ __nv_bfloat16 g_w_lo[GK * GK];
__device__ __nv_bfloat16 g_m_hi[GK * GK];     // M = W W^T split hi [i][j]
__device__ __nv_bfloat16 g_m_lo[GK * GK];
__device__ __nv_bfloat16 g_z_hi[NSUP * GK];   // Z = Xs M split hi [s][k]
__device__ __nv_bfloat16 g_z_lo[NSUP * GK];
__device__ float g_u[GK];                      // u = W b (fp32)
__device__ __nv_bfloat16 g_u_hi[GK];           // u split hi
__device__ __nv_bfloat16 g_u_lo[GK];           // u split lo
__device__ float g_bb[1];                      // b.b
__device__ float g_ds[NSUP];                   // d_j = x_j . u
__device__ float g_inv[NSUP];                  // inv support norms

// ---------------------------------------------------------------------------
// PTX helpers (plain sm_80+ only — legal at compute_103 non-'a')
// ---------------------------------------------------------------------------
__device__ __forceinline__ uint32_t smem_u32(const void* p) {
    uint32_t a;
    asm("{ .reg .u64 t; cvta.to.shared.u64 t, %1; cvt.u32.u64 %0, t; }" : "=r"(a) : "l"(p));
    return a;
}
__device__ __forceinline__ void ldsm4(uint32_t* r, uint32_t addr) {
    asm volatile("ldmatrix.sync.aligned.m8n8.x4.shared.b16 {%0,%1,%2,%3}, [%4];"
                 : "=r"(r[0]), "=r"(r[1]), "=r"(r[2]), "=r"(r[3]) : "r"(addr));
}
__device__ __forceinline__ void mma_bf16(float* d, const uint32_t* a, uint32_t b0, uint32_t b1) {
    asm volatile("mma.sync.aligned.m16n8k16.row.col.f32.bf16.bf16.f32 "
                 "{%0,%1,%2,%3}, {%4,%5,%6,%7}, {%8,%9}, {%0,%1,%2,%3};"
                 : "+f"(d[0]), "+f"(d[1]), "+f"(d[2]), "+f"(d[3])
                 : "r"(a[0]), "r"(a[1]), "r"(a[2]), "r"(a[3]), "r"(b0), "r"(b1));
}
__device__ __forceinline__ void cp_async16(uint32_t dst, const void* src) {
    asm volatile("cp.async.ca.shared.global [%0], [%1], 16;" :: "r"(dst), "l"(src));
}
#define CP_COMMIT() asm volatile("cp.async.commit_group;" ::: "memory")
#define CP_WAIT0()  asm volatile("cp.async.wait_group 0;"  ::: "memory")

__device__ __forceinline__ void split2(float x, float y, uint32_t& h, uint32_t& l) {
    __nv_bfloat162 hh = __floats2bfloat162_rn(x, y);
    __nv_bfloat162 ll = __floats2bfloat162_rn(x - __low2float(hh), y - __high2float(hh));
    h = *reinterpret_cast<uint32_t*>(&hh);
    l = *reinterpret_cast<uint32_t*>(&ll);
}

// ---------------------------------------------------------------------------
// Elementwise split of W into bf16 hi/lo
// ---------------------------------------------------------------------------
__global__ __launch_bounds__(256)
void split_w(const float* __restrict__ W) {
    const size_t i = ((size_t)blockIdx.x * 256 + threadIdx.x) * 4;
    float4 v = *(const float4*)(W + i);
    uint32_t h0, l0, h1, l1;
    split2(v.x, v.y, h0, l0);
    split2(v.z, v.w, h1, l1);
    *(uint2*)(g_w_hi + i) = make_uint2(h0, h1);
    *(uint2*)(g_w_lo + i) = make_uint2(l0, l1);
}

// ---------------------------------------------------------------------------
// u[k] = sum_n W[k,n] b[n]  (fp32 + split bf16)
// ---------------------------------------------------------------------------
__global__ void wb_kernel(const float* __restrict__ W, const float* __restrict__ b) {
    const int row = blockIdx.x;
    const float* p = W + (size_t)row * GK;
    float sum = 0.0f;
    for (int k = threadIdx.x * 4; k < GK; k += 1024) {
        float4 w4 = *(const float4*)(p + k);
        float4 b4 = *(const float4*)(b + k);
        sum = fmaf(w4.x, b4.x, sum); sum = fmaf(w4.y, b4.y, sum);
        sum = fmaf(w4.z, b4.z, sum); sum = fmaf(w4.w, b4.w, sum);
    }
#pragma unroll
    for (int o = 16; o > 0; o >>= 1) sum += __shfl_down_sync(0xFFFFFFFF, sum, o);
    __shared__ float ws[8];
    if ((threadIdx.x & 31) == 0) ws[threadIdx.x >> 5] = sum;
    __syncthreads();
    if (threadIdx.x == 0) {
        float t = 0.0f;
#pragma unroll
        for (int w = 0; w < 8; w++) t += ws[w];
        g_u[row] = t;
        __nv_bfloat16 h = __float2bfloat16_rn(t);
        g_u_hi[row] = h;
        g_u_lo[row] = __float2bfloat16_rn(t - __bfloat162float(h));
    }
}

__global__ void bb_kernel(const float* __restrict__ b) {
    float sum = 0.0f;
    for (int k = threadIdx.x; k < GK; k += 256) { float v = b[k]; sum = fmaf(v, v, sum); }
#pragma unroll
    for (int o = 16; o > 0; o >>= 1) sum += __shfl_down_sync(0xFFFFFFFF, sum, o);
    __shared__ float ws[8];
    if ((threadIdx.x & 31) == 0) ws[threadIdx.x >> 5] = sum;
    __syncthreads();
    if (threadIdx.x == 0) {
        float t = 0.0f;
#pragma unroll
        for (int w = 0; w < 8; w++) t += ws[w];
        g_bb[0] = t;
    }
}

// ---------------------------------------------------------------------------
// Support norms: |s_j|^2 = x_j.z_j + 2 x_j.u + bb ; also store d_j = x_j.u
// ---------------------------------------------------------------------------
__global__ void znorm_kernel(const float* __restrict__ Xs) {
    const int row = blockIdx.x;
    const float* x = Xs + (size_t)row * GK;
    const __nv_bfloat16* zh = g_z_hi + (size_t)row * GK;
    const __nv_bfloat16* zl = g_z_lo + (size_t)row * GK;
    float s1 = 0.0f, s2 = 0.0f;
    for (int k = threadIdx.x * 4; k < GK; k += 1024) {
        float4 x4 = *(const float4*)(x + k);
        float4 u4 = *(const float4*)(g_u + k);
        uint2 zh2 = *(const uint2*)(zh + k);
        uint2 zl2 = *(const uint2*)(zl + k);
        __nv_bfloat162 h0 = *(__nv_bfloat162*)&zh2.x, h1 = *(__nv_bfloat162*)&zh2.y;
        __nv_bfloat162 l0 = *(__nv_bfloat162*)&zl2.x, l1 = *(__nv_bfloat162*)&zl2.y;
        s1 = fmaf(__low2float(h0) + __low2float(l0), x4.x, s1);
        s1 = fmaf(__high2float(h0) + __high2float(l0), x4.y, s1);
        s1 = fmaf(__low2float(h1) + __low2float(l1), x4.z, s1);
        s1 = fmaf(__high2float(h1) + __high2float(l1), x4.w, s1);
        s2 = fmaf(x4.x, u4.x, s2); s2 = fmaf(x4.y, u4.y, s2);
        s2 = fmaf(x4.z, u4.z, s2); s2 = fmaf(x4.w, u4.w, s2);
    }
#pragma unroll
    for (int o = 16; o > 0; o >>= 1) {
        s1 += __shfl_down_sync(0xFFFFFFFF, s1, o);
        s2 += __shfl_down_sync(0xFFFFFFFF, s2, o);
    }
    __shared__ float w1[8], w2[8];
    if ((threadIdx.x & 31) == 0) { w1[threadIdx.x >> 5] = s1; w2[threadIdx.x >> 5] = s2; }
    __syncthreads();
    if (threadIdx.x == 0) {
        float t1 = 0.0f, t2 = 0.0f;
#pragma unroll
        for (int w = 0; w < 8; w++) { t1 += w1[w]; t2 += w2[w]; }
        float n2 = t1 + 2.0f * t2 + g_bb[0];
        g_inv[row] = rsqrtf(fmaxf(n2, 1e-10f));
        g_ds[row] = t2;
    }
}

// ---------------------------------------------------------------------------
// Split-bf16 GEMM (HMMA): O = A @ B^T. 3 terms, fp32 acc, split bf16 out.
// Non-TRI (Z): BM=128, BN=128, 256 thr (2x4 warps, tile 64x32), 2 CTA/SM.
// TRI (M):     BM=128, BN=64,  256 thr (2x4 warps, tile 64x16), 2 CTA/SM,
//              flat triangular 272-CTA grid (all resident), mirror later.
// ---------------------------------------------------------------------------
#define BKC 32
#define NCHUNK (GK / BKC)
#define ROWB 80

template <bool AFP32, bool TRI>
__global__ __launch_bounds__(256, 2)
void gemm_split(const float* __restrict__ Afp,
                const __nv_bfloat16* __restrict__ AhiG, const __nv_bfloat16* __restrict__ AloG,
                const __nv_bfloat16* __restrict__ Bhi, const __nv_bfloat16* __restrict__ Blo,
                __nv_bfloat16* __restrict__ Ohi, __nv_bfloat16* __restrict__ Olo) {
    constexpr int BN = TRI ? 64 : 128;       // N tile width
    constexpr int NW = BN / 4;               // cols per n-warp (16 or 32)
    constexpr int NACC = BN / 64;            // n8-frag pairs per warp (... NACC*2 frags)
    constexpr uint32_t OFF_ALO = 128 * ROWB;
    constexpr uint32_t OFF_BHI = 2 * 128 * ROWB;
    constexpr uint32_t OFF_BLO = OFF_BHI + BN * ROWB;
    constexpr uint32_t STAGEB  = OFF_BLO + BN * ROWB;

    int bx, by;
    if (TRI) {
        int i = blockIdx.x;
        int t = 0;
        while ((t + 1) * (t + 2) <= i) t++;   // cum(t) = t*(t+1), row t has 2t+2 tiles
        by = t;
        bx = i - t * (t + 1);
    } else {
        bx = blockIdx.x; by = blockIdx.y;
    }
    extern __shared__ __align__(128) char smem[];
    const uint32_t sb = smem_u32(smem);
    const int tid = threadIdx.x;
    const int lane = tid & 31, warp = tid >> 5;
    const int wm = warp & 1, wn = warp >> 1;   // 2 x 4 warp grid

    const float* Ab = AFP32 ? (Afp + (size_t)(by * 128) * GK) : nullptr;
    const __nv_bfloat16* AhiB = AFP32 ? nullptr : (AhiG + (size_t)(by * 128) * GK);
    const __nv_bfloat16* AloB = AFP32 ? nullptr : (AloG + (size_t)(by * 128) * GK);
    const size_t bn0 = (size_t)(bx * BN);

    float4 areg[4];
    auto loadA = [&](int k0) {
#pragma unroll
        for (int i = 0; i < 4; i++) {
            int task = tid + i * 256;
            areg[i] = *(const float4*)(Ab + (size_t)(task >> 3) * GK + k0 + (task & 7) * 4);
        }
    };
    auto storeA = [&](uint32_t stoff) {
#pragma unroll
        for (int i = 0; i < 4; i++) {
            int task = tid + i * 256;
            int row = task >> 3, c4 = task & 7;
            uint32_t h0, l0, h1, l1;
            split2(areg[i].x, areg[i].y, h0, l0);
            split2(areg[i].z, areg[i].w, h1, l1);
            *(uint2*)(smem + stoff + row * ROWB + c4 * 8) = make_uint2(h0, h1);
            *(uint2*)(smem + stoff + OFF_ALO + row * ROWB + c4 * 8) = make_uint2(l0, l1);
        }
    };
    auto cpA = [&](int k0, uint32_t stage) {
#pragma unroll
        for (int i = 0; i < 2; i++) {
            int task = tid + i * 256;
            int row = task >> 2, ch = task & 3;
            cp_async16(stage + row * ROWB + ch * 16, AhiB + (size_t)row * GK + k0 + ch * 8);
            cp_async16(stage + OFF_ALO + row * ROWB + ch * 16, AloB + (size_t)row * GK + k0 + ch * 8);
        }
    };
    auto loadB = [&](int k0, uint32_t stage) {
#pragma unroll
        for (int i = 0; i < (TRI ? 1 : 2); i++) {
            int task = tid + i * 256;
            int row = task >> 2, ch = task & 3;
            cp_async16(stage + OFF_BHI + row * ROWB + ch * 16, Bhi + (bn0 + row) * GK + k0 + ch * 8);
            cp_async16(stage + OFF_BLO + row * ROWB + ch * 16, Blo + (bn0 + row) * GK + k0 + ch * 8);
        }
        CP_COMMIT();
    };

    const uint32_t a_lane_off = (uint32_t)((wm * 64 + (lane & 15)) * ROWB + (lane >> 4) * 16);
    const uint32_t b_lane_off = (uint32_t)((wn * NW + ((lane >> 4) << 3) + (lane & 7)) * ROWB
                                           + ((lane >> 3) & 1) * 16);

    float acc[4][2 * NACC][4];
#pragma unroll
    for (int mi = 0; mi < 4; mi++)
#pragma unroll
        for (int ni = 0; ni < 2 * NACC; ni++)
#pragma unroll
            for (int j = 0; j < 4; j++) acc[mi][ni][j] = 0.0f;

    if (AFP32) { loadA(0); } else { cpA(0, sb); }
    loadB(0, sb);
    if (AFP32) storeA(0);
    CP_WAIT0();
    __syncthreads();

    for (int c = 0; c < NCHUNK; c++) {
        const uint32_t stoff = (uint32_t)((c & 1) * STAGEB);
        const uint32_t nxoff = (uint32_t)(((c + 1) & 1) * STAGEB);
        const bool more = (c + 1 < NCHUNK);
        if (more) {
            if (AFP32) loadA((c + 1) * BKC); else cpA((c + 1) * BKC, sb + nxoff);
            loadB((c + 1) * BKC, sb + nxoff);
        }

#pragma unroll
        for (int kk = 0; kk < 2; kk++) {
            const uint32_t kb = kk * 32;
            uint32_t ah[4][4], al[4][4], bh[NACC][4], bl[NACC][4];
#pragma unroll
            for (int mi = 0; mi < 4; mi++)
                ldsm4(ah[mi], sb + stoff + a_lane_off + mi * (16 * ROWB) + kb);
#pragma unroll
            for (int nj = 0; nj < NACC; nj++) {
                ldsm4(bh[nj], sb + stoff + OFF_BHI + b_lane_off + nj * (16 * ROWB) + kb);
                ldsm4(bl[nj], sb + stoff + OFF_BLO + b_lane_off + nj * (16 * ROWB) + kb);
            }
#pragma unroll
            for (int mi = 0; mi < 4; mi++)
#pragma unroll
                for (int ni = 0; ni < 2 * NACC; ni++)
                    mma_bf16(acc[mi][ni], ah[mi], bh[ni >> 1][(ni & 1) * 2], bh[ni >> 1][(ni & 1) * 2 + 1]);
#pragma unroll
            for (int mi = 0; mi < 4; mi++)
#pragma unroll
                for (int ni = 0; ni < 2 * NACC; ni++)
                    mma_bf16(acc[mi][ni], ah[mi], bl[ni >> 1][(ni & 1) * 2], bl[ni >> 1][(ni & 1) * 2 + 1]);
#pragma unroll
            for (int mi = 0; mi < 4; mi++)
                ldsm4(al[mi], sb + stoff + OFF_ALO + a_lane_off + mi * (16 * ROWB) + kb);
#pragma unroll
            for (int mi = 0; mi < 4; mi++)
#pragma unroll
                for (int ni = 0; ni < 2 * NACC; ni++)
                    mma_bf16(acc[mi][ni], al[mi], bh[ni >> 1][(ni & 1) * 2], bh[ni >> 1][(ni & 1) * 2 + 1]);
        }

        if (more && AFP32) storeA(nxoff);
        CP_WAIT0();
        __syncthreads();
    }

    const int gid = lane >> 2, tig = lane & 3;
#pragma unroll
    for (int mi = 0; mi < 4; mi++) {
        const int r0 = by * 128 + wm * 64 + mi * 16 + gid;
#pragma unroll
        for (int ni = 0; ni < 2 * NACC; ni++) {
            const int col = bx * BN + wn * NW + ni * 8 + tig * 2;
            uint32_t h, l;
            split2(acc[mi][ni][0], acc[mi][ni][1], h, l);
            *(uint32_t*)(Ohi + (size_t)r0 * GK + col) = h;
            *(uint32_t*)(Olo + (size_t)r0 * GK + col) = l;
            split2(acc[mi][ni][2], acc[mi][ni][3], h, l);
            *(uint32_t*)(Ohi + (size_t)(r0 + 8) * GK + col) = h;
            *(uint32_t*)(Olo + (size_t)(r0 + 8) * GK + col) = l;
        }
    }
}

#define GEMM_SMEM_Z   (2 * (4 * 128 * ROWB))                 // 81920
#define GEMM_SMEM_TRI (2 * (2 * 128 * ROWB + 2 * 64 * ROWB)) // 61440

// ---------------------------------------------------------------------------
// Mirror M's upper triangle from computed lower triangle (smem transpose).
// ---------------------------------------------------------------------------
__global__ __launch_bounds__(256)
void mirror_m() {
    if (blockIdx.x < blockIdx.y) return;
    const int a = blockIdx.y * 32, b = blockIdx.x * 32;
    __shared__ __nv_bfloat16 th[32][33], tl[32][33];
    const int tx = threadIdx.x & 31, ty = threadIdx.x >> 5;
#pragma unroll
    for (int i = 0; i < 4; i++) {
        int r = ty + i * 8;
        th[r][tx] = g_m_hi[(size_t)(b + r) * GK + a + tx];
        tl[r][tx] = g_m_lo[(size_t)(b + r) * GK + a + tx];
    }
    __syncthreads();
    const bool diag = (blockIdx.x == blockIdx.y);
#pragma unroll
    for (int i = 0; i < 4; i++) {
        int r = ty + i * 8;
        int row = a + r, col = b + tx;
        if (!diag || col > row) {
            g_m_hi[(size_t)row * GK + col] = th[tx][r];
            g_m_lo[(size_t)row * GK + col] = tl[tx][r];
        }
    }
}

// ---------------------------------------------------------------------------
// Fused attention via HMMA: grid (4, 64) = 256 CTAs, 2/SM, single wave.
// 80 query rows (75 valid) x 128 support cols; 320 threads = 10 warps
// (5m x 2n), warp tile 16x64. B pad rows 100..127 hold u -> acc col 127 is
// dq_i = x_i.u. simT overlays the dead stage buffers.
// ---------------------------------------------------------------------------
#define NV 75
#define AT_ROWB 80
#define AT_ALO  (80 * AT_ROWB)                 // 6400
#define AT_BHI  (2 * 80 * AT_ROWB)             // 12800
#define AT_BLO  (AT_BHI + 128 * AT_ROWB)       // 23040
#define AT_STAGE (AT_BLO + 128 * AT_ROWB)      // 33280
#define SIMW 132
#define AT_SMEM (2 * AT_STAGE)                 // 66560 (simT overlays stages)

__global__ __launch_bounds__(320, 2)
void attention_mma(const float* __restrict__ query, const float* __restrict__ onehot,
                   float* __restrict__ out, int out_size) {
    extern __shared__ __align__(128) char smem[];
    __shared__ float invn[SPE], dscol[SPE];
    __shared__ int lab[SPE];
    __shared__ float probsS[80][NCLS];
    const uint32_t sb = smem_u32(smem);
    const int tid = threadIdx.x, lane = tid & 31, warp = tid >> 5;
    const int wm = warp >> 1, wn = warp & 1;   // 5 x 2
    const int t = blockIdx.x, e = blockIdx.y;
    const int qbase = e * QPE + t * NV;
    const int sbase = e * SPE;

    if (tid < SPE) {
        invn[tid] = g_inv[sbase + tid];
        dscol[tid] = g_ds[sbase + tid];
        const float* oh = onehot + (size_t)(e * SPE + tid) * NCLS;
        int l = 0;
        float best = oh[0];
#pragma unroll
        for (int c = 1; c < NCLS; c++) { float v = oh[c]; if (v > best) { best = v; l = c; } }
        lab[tid] = l;
    }

    float4 areg[2];
    auto loadA = [&](int k0) {
#pragma unroll
        for (int i = 0; i < 2; i++) {
            int task = tid + i * 320;       // 640 tasks = 80 rows x 8 chunks
            int row = task >> 3, c4 = task & 7;
            int qr = qbase + min(row, NV - 1);
            areg[i] = *(const float4*)(query + (size_t)qr * GK + k0 + c4 * 4);
        }
    };
    auto storeA = [&](uint32_t stoff) {
#pragma unroll
        for (int i = 0; i < 2; i++) {
            int task = tid + i * 320;
            int row = task >> 3, c4 = task & 7;
            uint32_t h0, l0, h1, l1;
            split2(areg[i].x, areg[i].y, h0, l0);
            split2(areg[i].z, areg[i].w, h1, l1);
            *(uint2*)(smem + stoff + row * AT_ROWB + c4 * 8) = make_uint2(h0, h1);
            *(uint2*)(smem + stoff + AT_ALO + row * AT_ROWB + c4 * 8) = make_uint2(l0, l1);
        }
    };
    auto loadB = [&](int k0, uint32_t stage) {
        for (int idx = tid; idx < 512; idx += 320) {   // 128 rows x 4 chunks
            int row = idx >> 2, ch = idx & 3;
            const __nv_bfloat16* srch;
            const __nv_bfloat16* srcl;
            if (row < SPE) {
                srch = g_z_hi + (size_t)(sbase + row) * GK + k0 + ch * 8;
                srcl = g_z_lo + (size_t)(sbase + row) * GK + k0 + ch * 8;
            } else {   // padding rows carry u -> acc col = x.u (dq)
                srch = g_u_hi + k0 + ch * 8;
                srcl = g_u_lo + k0 + ch * 8;
            }
            cp_async16(stage + AT_BHI + row * AT_ROWB + ch * 16, srch);
            cp_async16(stage + AT_BLO + row * AT_ROWB + ch * 16, srcl);
        }
        CP_COMMIT();
    };

    const uint32_t a_lane_off = (uint32_t)((wm * 16 + (lane & 15)) * AT_ROWB + (lane >> 4) * 16);
    const uint32_t b_lane_off = (uint32_t)((wn * 64 + ((lane >> 4) << 3) + (lane & 7)) * AT_ROWB
                                           + ((lane >> 3) & 1) * 16);

    float acc[8][4];
#pragma unroll
    for (int nf = 0; nf < 8; nf++)
#pragma unroll
        for (int j = 0; j < 4; j++) acc[nf][j] = 0.0f;

    loadA(0);
    loadB(0, sb);
    storeA(0);
    CP_WAIT0();
    __syncthreads();

    for (int c = 0; c < NCHUNK; c++) {
        const uint32_t stoff = (uint32_t)((c & 1) * AT_STAGE);
        const uint32_t nxoff = (uint32_t)(((c + 1) & 1) * AT_STAGE);
        const bool more = (c + 1 < NCHUNK);
        if (more) { loadA((c + 1) * BKC); loadB((c + 1) * BKC, sb + nxoff); }

#pragma unroll
        for (int kk = 0; kk < 2; kk++) {
            const uint32_t kb = kk * 32;
            uint32_t ah[4], al[4], bh[4][4], bl[4][4];
            ldsm4(ah, sb + stoff + a_lane_off + kb);
#pragma unroll
            for (int nj = 0; nj < 4; nj++)
                ldsm4(bh[nj], sb + stoff + AT_BHI + b_lane_off + nj * (16 * AT_ROWB) + kb);
            // term 1: Ahi x Bhi
#pragma unroll
            for (int nf = 0; nf < 8; nf++)
                mma_bf16(acc[nf], ah, bh[nf >> 1][(nf & 1) * 2], bh[nf >> 1][(nf & 1) * 2 + 1]);
            // term 3: Alo x Bhi (then bh dead -> regs reusable by bl)
            ldsm4(al, sb + stoff + AT_ALO + a_lane_off + kb);
#pragma unroll
            for (int nf = 0; nf < 8; nf++)
                mma_bf16(acc[nf], al, bh[nf >> 1][(nf & 1) * 2], bh[nf >> 1][(nf & 1) * 2 + 1]);
            // term 2: Ahi x Blo
#pragma unroll
            for (int nj = 0; nj < 4; nj++)
                ldsm4(bl[nj], sb + stoff + AT_BLO + b_lane_off + nj * (16 * AT_ROWB) + kb);
#pragma unroll
            for (int nf = 0; nf < 8; nf++)
                mma_bf16(acc[nf], ah, bl[nf >> 1][(nf & 1) * 2], bl[nf >> 1][(nf & 1) * 2 + 1]);
        }

        if (more) storeA(nxoff);
        CP_WAIT0();
        __syncthreads();
    }

    // epilogue: write RAW acc into simT (overlays dead stage buffers)
    float* simT = (float*)smem;
    const int gid = lane >> 2, tig = lane & 3;
    {
        const int r = wm * 16 + gid;
#pragma unroll
        for (int nf = 0; nf < 8; nf++) {
            const int cb = wn * 64 + nf * 8 + tig * 2;
            simT[r * SIMW + cb]           = acc[nf][0];
            simT[r * SIMW + cb + 1]       = acc[nf][1];
            simT[(r + 8) * SIMW + cb]     = acc[nf][2];
            simT[(r + 8) * SIMW + cb + 1] = acc[nf][3];
        }
    }
    __syncthreads();

    // softmax + label bucketing; col 127 holds dq_i = x_i.u
    if (tid < NV) {
        const int r = tid;
        const float dqbb = simT[r * SIMW + 127] + g_bb[0];
        float m = -1e30f;
#pragma unroll 4
        for (int ss = 0; ss < SPE; ss++) {
            float v = (simT[r * SIMW + ss] + dqbb + dscol[ss]) * invn[ss];
            m = fmaxf(m, v);
        }
        float* p = probsS[r];
#pragma unroll
        for (int c = 0; c < NCLS; c++) p[c] = 0.0f;
        float sum = 0.0f;
        for (int ss = 0; ss < SPE; ss++) {
            float v = (simT[r * SIMW + ss] + dqbb + dscol[ss]) * invn[ss];
            float w = expf(v - m);
            sum += w;
            p[lab[ss]] += w;
        }
        const float invsum = 1.0f / sum;
        const int grow = qbase + r;
        int bestc = 0;
        float bestv = p[0];
#pragma unroll
        for (int c = 0; c < NCLS; c++) {
            float v = p[c] * invsum;
            out[(size_t)grow * NCLS + c] = v;
            if (p[c] > bestv) { bestv = p[c]; bestc = c; }
        }
        if (out_size >= NQRY * NCLS + NQRY)
            out[NQRY * NCLS + grow] = (float)bestc;
    }
}

// ---------------------------------------------------------------------------
extern "C" void kernel_launch(void* const* d_in, const int* in_sizes, int n_in,
                              void* d_out, int out_size) {
    const float* support = (const float*)d_in[0];
    const float* query   = (const float*)d_in[1];
    const float* onehot  = (const float*)d_in[2];
    const float* W       = (const float*)d_in[3];
    const float* b       = (const float*)d_in[4];
    float* out = (float*)d_out;

    __nv_bfloat16 *whi, *wlo, *mhi, *mlo, *zhi, *zlo;
    cudaGetSymbolAddress((void**)&whi, g_w_hi);
    cudaGetSymbolAddress((void**)&wlo, g_w_lo);
    cudaGetSymbolAddress((void**)&mhi, g_m_hi);
    cudaGetSymbolAddress((void**)&mlo, g_m_lo);
    cudaGetSymbolAddress((void**)&zhi, g_z_hi);
    cudaGetSymbolAddress((void**)&zlo, g_z_lo);

    cudaFuncSetAttribute((const void*)gemm_split<false, true>,
                         cudaFuncAttributeMaxDynamicSharedMemorySize, GEMM_SMEM_TRI);
    cudaFuncSetAttribute((const void*)gemm_split<true, false>,
                         cudaFuncAttributeMaxDynamicSharedMemorySize, GEMM_SMEM_Z);
    cudaFuncSetAttribute((const void*)attention_mma,
                         cudaFuncAttributeMaxDynamicSharedMemorySize, AT_SMEM);

    // 1. split W into bf16 hi/lo
    split_w<<<(GK * GK) / 1024, 256>>>(W);
    // 2. bias terms: u = W b (fp32 + split), bb = b.b
    wb_kernel<<<GK, 256>>>(W, b);
    bb_kernel<<<1, 256>>>(b);
    // 3. M = W W^T, lower triangle, flat 272-CTA half-width grid (2 CTA/SM)
    gemm_split<false, true><<<272, 256, GEMM_SMEM_TRI>>>(
        nullptr, whi, wlo, whi, wlo, mhi, mlo);
    mirror_m<<<dim3(64, 64), 256>>>();
    // 4. Z = Xs M
    gemm_split<true, false><<<dim3(16, NSUP / 128), 256, GEMM_SMEM_Z>>>(
        support, nullptr, nullptr, mhi, mlo, zhi, zlo);
    // 5. support norms + d_j (query dots folded into attention via u-rows)
    znorm_kernel<<<NSUP, 256>>>(support);
    // 6. fused attention sim/softmax/classify: 256 CTAs, 2/SM, one wave
    attention_mma<<<dim3(4, NEP), 320, AT_SMEM>>>(query, onehot, out, out_size);
}

// round 14
// speedup vs baseline: 1.0144x; 1.0144x over previous
#include <cuda_runtime.h>
#include <cuda_bf16.h>
#include <math.h>
#include <stdint.h>

// Problem constants: B=64, C=20, K=5, Q=15, D=H=2048
#define D_DIM 2048
#define GK    2048
#define NSUP  6400
#define NQRY  19200
#define NEP   64
#define SPE   100
#define QPE   300
#define NCLS  20

// Scratch (device globals: allocation-free per harness rules)
__device__ __nv_bfloat16 g_w_hi[GK * GK];      // W split hi  [k][n]
__device__ __nv_bfloat16 g_w_lo[GK * GK];
__device__ __nv_bfloat16 g_xs_hi[NSUP * GK];   // support split hi
__device__ __nv_bfloat16 g_xs_lo[NSUP * GK];
__device__ float g_mp[2 * GK * GK];            // M split-K fp32 partials
__device__ __nv_bfloat16 g_m_hi[GK * GK];      // M = W W^T split hi [i][j]
__device__ __nv_bfloat16 g_m_lo[GK * GK];
__device__ __nv_bfloat16 g_z_hi[NSUP * GK];    // Z = Xs M split hi [s][k]
__device__ __nv_bfloat16 g_z_lo[NSUP * GK];
__device__ float g_u[GK];                       // u = W b (fp32)
__device__ __nv_bfloat16 g_u_hi[GK];            // u split hi
__device__ __nv_bfloat16 g_u_lo[GK];            // u split lo
__device__ float g_bb[1];                       // b.b
__device__ float g_ds[NSUP];                    // d_j = x_j . u
__device__ float g_inv[NSUP];                   // inv support norms

// ---------------------------------------------------------------------------
// PTX helpers (plain sm_80+ only — legal at compute_103 non-'a')
// ---------------------------------------------------------------------------
__device__ __forceinline__ uint32_t smem_u32(const void* p) {
    uint32_t a;
    asm("{ .reg .u64 t; cvta.to.shared.u64 t, %1; cvt.u32.u64 %0, t; }" : "=r"(a) : "l"(p));
    return a;
}
__device__ __forceinline__ void ldsm4(uint32_t* r, uint32_t addr) {
    asm volatile("ldmatrix.sync.aligned.m8n8.x4.shared.b16 {%0,%1,%2,%3}, [%4];"
                 : "=r"(r[0]), "=r"(r[1]), "=r"(r[2]), "=r"(r[3]) : "r"(addr));
}
__device__ __forceinline__ void mma_bf16(float* d, const uint32_t* a, uint32_t b0, uint32_t b1) {
    asm volatile("mma.sync.aligned.m16n8k16.row.col.f32.bf16.bf16.f32 "
                 "{%0,%1,%2,%3}, {%4,%5,%6,%7}, {%8,%9}, {%0,%1,%2,%3};"
                 : "+f"(d[0]), "+f"(d[1]), "+f"(d[2]), "+f"(d[3])
                 : "r"(a[0]), "r"(a[1]), "r"(a[2]), "r"(a[3]), "r"(b0), "r"(b1));
}
__device__ __forceinline__ void cp_async16(uint32_t dst, const void* src) {
    asm volatile("cp.async.ca.shared.global [%0], [%1], 16;" :: "r"(dst), "l"(src));
}
#define CP_COMMIT() asm volatile("cp.async.commit_group;" ::: "memory")
#define CP_WAIT0()  asm volatile("cp.async.wait_group 0;"  ::: "memory")

__device__ __forceinline__ void split2(float x, float y, uint32_t& h, uint32_t& l) {
    __nv_bfloat162 hh = __floats2bfloat162_rn(x, y);
    __nv_bfloat162 ll = __floats2bfloat162_rn(x - __low2float(hh), y - __high2float(hh));
    h = *reinterpret_cast<uint32_t*>(&hh);
    l = *reinterpret_cast<uint32_t*>(&ll);
}

// ---------------------------------------------------------------------------
// Elementwise split into bf16 hi/lo (W and support)
// ---------------------------------------------------------------------------
__global__ __launch_bounds__(256)
void split_arr(const float* __restrict__ X,
               __nv_bfloat16* __restrict__ Hi, __nv_bfloat16* __restrict__ Lo) {
    const size_t i = ((size_t)blockIdx.x * 256 + threadIdx.x) * 4;
    float4 v = *(const float4*)(X + i);
    uint32_t h0, l0, h1, l1;
    split2(v.x, v.y, h0, l0);
    split2(v.z, v.w, h1, l1);
    *(uint2*)(Hi + i) = make_uint2(h0, h1);
    *(uint2*)(Lo + i) = make_uint2(l0, l1);
}

// ---------------------------------------------------------------------------
// u[k] = sum_n W[k,n] b[n]  (fp32 + split bf16)
// ---------------------------------------------------------------------------
__global__ void wb_kernel(const float* __restrict__ W, const float* __restrict__ b) {
    const int row = blockIdx.x;
    const float* p = W + (size_t)row * GK;
    float sum = 0.0f;
    for (int k = threadIdx.x * 4; k < GK; k += 1024) {
        float4 w4 = *(const float4*)(p + k);
        float4 b4 = *(const float4*)(b + k);
        sum = fmaf(w4.x, b4.x, sum); sum = fmaf(w4.y, b4.y, sum);
        sum = fmaf(w4.z, b4.z, sum); sum = fmaf(w4.w, b4.w, sum);
    }
#pragma unroll
    for (int o = 16; o > 0; o >>= 1) sum += __shfl_down_sync(0xFFFFFFFF, sum, o);
    __shared__ float ws[8];
    if ((threadIdx.x & 31) == 0) ws[threadIdx.x >> 5] = sum;
    __syncthreads();
    if (threadIdx.x == 0) {
        float t = 0.0f;
#pragma unroll
        for (int w = 0; w < 8; w++) t += ws[w];
        g_u[row] = t;
        __nv_bfloat16 h = __float2bfloat16_rn(t);
        g_u_hi[row] = h;
        g_u_lo[row] = __float2bfloat16_rn(t - __bfloat162float(h));
    }
}

__global__ void bb_kernel(const float* __restrict__ b) {
    float sum = 0.0f;
    for (int k = threadIdx.x; k < GK; k += 256) { float v = b[k]; sum = fmaf(v, v, sum); }
#pragma unroll
    for (int o = 16; o > 0; o >>= 1) sum += __shfl_down_sync(0xFFFFFFFF, sum, o);
    __shared__ float ws[8];
    if ((threadIdx.x & 31) == 0) ws[threadIdx.x >> 5] = sum;
    __syncthreads();
    if (threadIdx.x == 0) {
        float t = 0.0f;
#pragma unroll
        for (int w = 0; w < 8; w++) t += ws[w];
        g_bb[0] = t;
    }
}

// ---------------------------------------------------------------------------
// Support norms: |s_j|^2 = x_j.z_j + 2 x_j.u + bb ; also store d_j = x_j.u
// ---------------------------------------------------------------------------
__global__ void znorm_kernel(const float* __restrict__ Xs) {
    const int row = blockIdx.x;
    const float* x = Xs + (size_t)row * GK;
    const __nv_bfloat16* zh = g_z_hi + (size_t)row * GK;
    const __nv_bfloat16* zl = g_z_lo + (size_t)row * GK;
    float s1 = 0.0f, s2 = 0.0f;
    for (int k = threadIdx.x * 4; k < GK; k += 1024) {
        float4 x4 = *(const float4*)(x + k);
        float4 u4 = *(const float4*)(g_u + k);
        uint2 zh2 = *(const uint2*)(zh + k);
        uint2 zl2 = *(const uint2*)(zl + k);
        __nv_bfloat162 h0 = *(__nv_bfloat162*)&zh2.x, h1 = *(__nv_bfloat162*)&zh2.y;
        __nv_bfloat162 l0 = *(__nv_bfloat162*)&zl2.x, l1 = *(__nv_bfloat162*)&zl2.y;
        s1 = fmaf(__low2float(h0) + __low2float(l0), x4.x, s1);
        s1 = fmaf(__high2float(h0) + __high2float(l0), x4.y, s1);
        s1 = fmaf(__low2float(h1) + __low2float(l1), x4.z, s1);
        s1 = fmaf(__high2float(h1) + __high2float(l1), x4.w, s1);
        s2 = fmaf(x4.x, u4.x, s2); s2 = fmaf(x4.y, u4.y, s2);
        s2 = fmaf(x4.z, u4.z, s2); s2 = fmaf(x4.w, u4.w, s2);
    }
#pragma unroll
    for (int o = 16; o > 0; o >>= 1) {
        s1 += __shfl_down_sync(0xFFFFFFFF, s1, o);
        s2 += __shfl_down_sync(0xFFFFFFFF, s2, o);
    }
    __shared__ float w1[8], w2[8];
    if ((threadIdx.x & 31) == 0) { w1[threadIdx.x >> 5] = s1; w2[threadIdx.x >> 5] = s2; }
    __syncthreads();
    if (threadIdx.x == 0) {
        float t1 = 0.0f, t2 = 0.0f;
#pragma unroll
        for (int w = 0; w < 8; w++) { t1 += w1[w]; t2 += w2[w]; }
        float n2 = t1 + 2.0f * t2 + g_bb[0];
        g_inv[row] = rsqrtf(fmaxf(n2, 1e-10f));
        g_ds[row] = t2;
    }
}

// ---------------------------------------------------------------------------
// Split-bf16 GEMM (HMMA): O = A @ B^T, A/B presplit bf16, 3 terms, fp32 acc.
// BM=128, BN=128, BK=32, 256 thr (2x4 warps, warp tile 64x32), 2 CTA/SM.
// MSPLITK=false (Z): grid (16,50); output split bf16 hi/lo.
// MSPLITK=true  (M): flat grid 272 = 136 tri tiles x 2 K-halves (K=1024 each);
//                    output fp32 partials to Pout + kpart*GK*GK.
// ---------------------------------------------------------------------------
#define BKC 32
#define ROWB 80
#define OFF_ALO (128 * ROWB)
#define OFF_BHI (2 * 128 * ROWB)
#define OFF_BLO (3 * 128 * ROWB)
#define STAGEB  (4 * 128 * ROWB)          // 40960
#define GEMM_SMEM (2 * STAGEB)            // 81920

template <bool MSPLITK>
__global__ __launch_bounds__(256, 2)
void gemm_split(const __nv_bfloat16* __restrict__ AhiG, const __nv_bfloat16* __restrict__ AloG,
                const __nv_bfloat16* __restrict__ Bhi, const __nv_bfloat16* __restrict__ Blo,
                __nv_bfloat16* __restrict__ Ohi, __nv_bfloat16* __restrict__ Olo,
                float* __restrict__ Pout) {
    int bx, by, kpart = 0;
    if (MSPLITK) {
        int i = blockIdx.x;
        kpart = i & 1;
        int tix = i >> 1;
        int t = 0;
        while ((t + 1) * (t + 2) / 2 <= tix) t++;
        by = t;
        bx = tix - t * (t + 1) / 2;
    } else {
        bx = blockIdx.x; by = blockIdx.y;
    }
    const int kbase = MSPLITK ? kpart * (GK / 2) : 0;
    const int nchunk = MSPLITK ? (GK / 2 / BKC) : (GK / BKC);

    extern __shared__ __align__(128) char smem[];
    const uint32_t sb = smem_u32(smem);
    const int tid = threadIdx.x;
    const int lane = tid & 31, warp = tid >> 5;
    const int wm = warp & 1, wn = warp >> 1;   // 2 x 4 warp grid, tile 64x32

    const __nv_bfloat16* AhiB = AhiG + (size_t)(by * 128) * GK;
    const __nv_bfloat16* AloB = AloG + (size_t)(by * 128) * GK;
    const size_t bn0 = (size_t)(bx * 128);

    auto cpA = [&](int k0, uint32_t stage) {
#pragma unroll
        for (int i = 0; i < 2; i++) {
            int task = tid + i * 256;
            int row = task >> 2, ch = task & 3;
            cp_async16(stage + row * ROWB + ch * 16, AhiB + (size_t)row * GK + k0 + ch * 8);
            cp_async16(stage + OFF_ALO + row * ROWB + ch * 16, AloB + (size_t)row * GK + k0 + ch * 8);
        }
    };
    auto loadB = [&](int k0, uint32_t stage) {
#pragma unroll
        for (int i = 0; i < 2; i++) {
            int task = tid + i * 256;
            int row = task >> 2, ch = task & 3;
            cp_async16(stage + OFF_BHI + row * ROWB + ch * 16, Bhi + (bn0 + row) * GK + k0 + ch * 8);
            cp_async16(stage + OFF_BLO + row * ROWB + ch * 16, Blo + (bn0 + row) * GK + k0 + ch * 8);
        }
        CP_COMMIT();
    };

    const uint32_t a_lane_off = (uint32_t)((wm * 64 + (lane & 15)) * ROWB + (lane >> 4) * 16);
    const uint32_t b_lane_off = (uint32_t)((wn * 32 + ((lane >> 4) << 3) + (lane & 7)) * ROWB
                                           + ((lane >> 3) & 1) * 16);

    float acc[4][4][4];
#pragma unroll
    for (int mi = 0; mi < 4; mi++)
#pragma unroll
        for (int ni = 0; ni < 4; ni++)
#pragma unroll
            for (int j = 0; j < 4; j++) acc[mi][ni][j] = 0.0f;

    cpA(kbase, sb);
    loadB(kbase, sb);
    CP_WAIT0();
    __syncthreads();

    for (int c = 0; c < nchunk; c++) {
        const uint32_t stoff = (uint32_t)((c & 1) * STAGEB);
        const uint32_t nxoff = (uint32_t)(((c + 1) & 1) * STAGEB);
        const bool more = (c + 1 < nchunk);
        if (more) {
            cpA(kbase + (c + 1) * BKC, sb + nxoff);
            loadB(kbase + (c + 1) * BKC, sb + nxoff);
        }

#pragma unroll
        for (int kk = 0; kk < 2; kk++) {
            const uint32_t kb = kk * 32;
            uint32_t ah[4][4], al[4][4], bh[2][4], bl[2][4];
#pragma unroll
            for (int mi = 0; mi < 4; mi++)
                ldsm4(ah[mi], sb + stoff + a_lane_off + mi * (16 * ROWB) + kb);
#pragma unroll
            for (int nj = 0; nj < 2; nj++) {
                ldsm4(bh[nj], sb + stoff + OFF_BHI + b_lane_off + nj * (16 * ROWB) + kb);
                ldsm4(bl[nj], sb + stoff + OFF_BLO + b_lane_off + nj * (16 * ROWB) + kb);
            }
#pragma unroll
            for (int mi = 0; mi < 4; mi++)
#pragma unroll
                for (int ni = 0; ni < 4; ni++)
                    mma_bf16(acc[mi][ni], ah[mi], bh[ni >> 1][(ni & 1) * 2], bh[ni >> 1][(ni & 1) * 2 + 1]);
#pragma unroll
            for (int mi = 0; mi < 4; mi++)
#pragma unroll
                for (int ni = 0; ni < 4; ni++)
                    mma_bf16(acc[mi][ni], ah[mi], bl[ni >> 1][(ni & 1) * 2], bl[ni >> 1][(ni & 1) * 2 + 1]);
#pragma unroll
            for (int mi = 0; mi < 4; mi++)
                ldsm4(al[mi], sb + stoff + OFF_ALO + a_lane_off + mi * (16 * ROWB) + kb);
#pragma unroll
            for (int mi = 0; mi < 4; mi++)
#pragma unroll
                for (int ni = 0; ni < 4; ni++)
                    mma_bf16(acc[mi][ni], al[mi], bh[ni >> 1][(ni & 1) * 2], bh[ni >> 1][(ni & 1) * 2 + 1]);
        }

        CP_WAIT0();
        __syncthreads();
    }

    const int gid = lane >> 2, tig = lane & 3;
    if (MSPLITK) {
        float* P = Pout + (size_t)kpart * GK * GK;
#pragma unroll
        for (int mi = 0; mi < 4; mi++) {
            const int r0 = by * 128 + wm * 64 + mi * 16 + gid;
#pragma unroll
            for (int ni = 0; ni < 4; ni++) {
                const int col = bx * 128 + wn * 32 + ni * 8 + tig * 2;
                *(float2*)(P + (size_t)r0 * GK + col) = make_float2(acc[mi][ni][0], acc[mi][ni][1]);
                *(float2*)(P + (size_t)(r0 + 8) * GK + col) = make_float2(acc[mi][ni][2], acc[mi][ni][3]);
            }
        }
    } else {
#pragma unroll
        for (int mi = 0; mi < 4; mi++) {
            const int r0 = by * 128 + wm * 64 + mi * 16 + gid;
#pragma unroll
            for (int ni = 0; ni < 4; ni++) {
                const int col = bx * 128 + wn * 32 + ni * 8 + tig * 2;
                uint32_t h, l;
                split2(acc[mi][ni][0], acc[mi][ni][1], h, l);
                *(uint32_t*)(Ohi + (size_t)r0 * GK + col) = h;
                *(uint32_t*)(Olo + (size_t)r0 * GK + col) = l;
                split2(acc[mi][ni][2], acc[mi][ni][3], h, l);
                *(uint32_t*)(Ohi + (size_t)(r0 + 8) * GK + col) = h;
                *(uint32_t*)(Olo + (size_t)(r0 + 8) * GK + col) = l;
            }
        }
    }
}

// ---------------------------------------------------------------------------
// Combine split-K partials -> split bf16 M, with fused mirror to upper tri.
// Grid (136, 16): flat lower-tri 128-tile x 32x32 subtile. 256 threads.
// Diagonal tiles skip the transposed write (fully computed; avoids races).
// ---------------------------------------------------------------------------
__global__ __launch_bounds__(256)
void combine_m() {
    int tix = blockIdx.x;
    int t = 0;
    while ((t + 1) * (t + 2) / 2 <= tix) t++;
    const int BY = t, BX = tix - t * (t + 1) / 2;
    const int sy = blockIdx.y >> 2, sx = blockIdx.y & 3;
    const int rowbase = BY * 128 + sy * 32, colbase = BX * 128 + sx * 32;

    __shared__ __nv_bfloat16 sh[32][33], sl[32][33];
    const int tx = threadIdx.x & 31, ty = threadIdx.x >> 5;
    const float* P0 = g_mp;
    const float* P1 = g_mp + (size_t)GK * GK;

#pragma unroll
    for (int i = 0; i < 4; i++) {
        int r = ty + i * 8;
        size_t idx = (size_t)(rowbase + r) * GK + colbase + tx;
        float v = P0[idx] + P1[idx];
        __nv_bfloat16 h = __float2bfloat16_rn(v);
        __nv_bfloat16 l = __float2bfloat16_rn(v - __bfloat162float(h));
        g_m_hi[idx] = h;
        g_m_lo[idx] = l;
        sh[r][tx] = h;
        sl[r][tx] = l;
    }
    if (BY == BX) return;   // diagonal tile fully computed; no mirror needed
    __syncthreads();
#pragma unroll
    for (int i = 0; i < 4; i++) {
        int r = ty + i * 8;
        size_t idx = (size_t)(colbase + r) * GK + rowbase + tx;
        g_m_hi[idx] = sh[tx][r];
        g_m_lo[idx] = sl[tx][r];
    }
}

// ---------------------------------------------------------------------------
// Fused attention via HMMA (R12 config): grid (2, 64); 160 query rows (150
// valid) x 128 support cols. B pad rows 100..127 hold u -> acc col 127 is
// dq_i = x_i.u. 320 threads = 10 warps (5m x 2n), warp tile 32x64. simT
// overlays the dead stage buffers.
// ---------------------------------------------------------------------------
#define NV 150
#define AT_ROWB 80
#define AT_ALO  (160 * AT_ROWB)
#define AT_BHI  (2 * 160 * AT_ROWB)
#define AT_BLO  (AT_BHI + 128 * AT_ROWB)
#define AT_STAGE (AT_BLO + 128 * AT_ROWB)      // 46080
#define SIMW 132
#define AT_SMEM (2 * AT_STAGE)                 // 92160 (simT overlays stages)
#define NCHUNK_AT (GK / BKC)

__global__ __launch_bounds__(320, 1)
void attention_mma(const float* __restrict__ query, const float* __restrict__ onehot,
                   float* __restrict__ out, int out_size) {
    extern __shared__ __align__(128) char smem[];
    __shared__ float invn[SPE], dscol[SPE];
    __shared__ int lab[SPE];
    __shared__ float probsS[160][NCLS];
    const uint32_t sb = smem_u32(smem);
    const int tid = threadIdx.x, lane = tid & 31, warp = tid >> 5;
    const int wm = warp >> 1, wn = warp & 1;   // 5 x 2
    const int t = blockIdx.x, e = blockIdx.y;
    const int qbase = e * QPE + t * NV;
    const int sbase = e * SPE;

    if (tid < SPE) {
        invn[tid] = g_inv[sbase + tid];
        dscol[tid] = g_ds[sbase + tid];
        const float* oh = onehot + (size_t)(e * SPE + tid) * NCLS;
        int l = 0;
        float best = oh[0];
#pragma unroll
        for (int c = 1; c < NCLS; c++) { float v = oh[c]; if (v > best) { best = v; l = c; } }
        lab[tid] = l;
    }

    float4 areg[4];
    auto loadA = [&](int k0) {
#pragma unroll
        for (int i = 0; i < 4; i++) {
            int task = tid + i * 320;       // 1280 tasks = 160 rows x 8 chunks
            int row = task >> 3, c4 = task & 7;
            int qr = qbase + min(row, NV - 1);
            areg[i] = *(const float4*)(query + (size_t)qr * GK + k0 + c4 * 4);
        }
    };
    auto storeA = [&](uint32_t stoff) {
#pragma unroll
        for (int i = 0; i < 4; i++) {
            int task = tid + i * 320;
            int row = task >> 3, c4 = task & 7;
            uint32_t h0, l0, h1, l1;
            split2(areg[i].x, areg[i].y, h0, l0);
            split2(areg[i].z, areg[i].w, h1, l1);
            *(uint2*)(smem + stoff + row * AT_ROWB + c4 * 8) = make_uint2(h0, h1);
            *(uint2*)(smem + stoff + AT_ALO + row * AT_ROWB + c4 * 8) = make_uint2(l0, l1);
        }
    };
    auto loadB = [&](int k0, uint32_t stage) {
        for (int idx = tid; idx < 512; idx += 320) {   // 128 rows x 4 chunks
            int row = idx >> 2, ch = idx & 3;
            const __nv_bfloat16* srch;
            const __nv_bfloat16* srcl;
            if (row < SPE) {
                srch = g_z_hi + (size_t)(sbase + row) * GK + k0 + ch * 8;
                srcl = g_z_lo + (size_t)(sbase + row) * GK + k0 + ch * 8;
            } else {   // padding rows carry u -> acc col = x.u (dq)
                srch = g_u_hi + k0 + ch * 8;
                srcl = g_u_lo + k0 + ch * 8;
            }
            cp_async16(stage + AT_BHI + row * AT_ROWB + ch * 16, srch);
            cp_async16(stage + AT_BLO + row * AT_ROWB + ch * 16, srcl);
        }
        CP_COMMIT();
    };

    const uint32_t a_lane_off = (uint32_t)((wm * 32 + (lane & 15)) * AT_ROWB + (lane >> 4) * 16);
    const uint32_t b_lane_off = (uint32_t)((wn * 64 + ((lane >> 4) << 3) + (lane & 7)) * AT_ROWB
                                           + ((lane >> 3) & 1) * 16);

    float acc[2][8][4];
#pragma unroll
    for (int mi = 0; mi < 2; mi++)
#pragma unroll
        for (int nf = 0; nf < 8; nf++)
#pragma unroll
            for (int j = 0; j < 4; j++) acc[mi][nf][j] = 0.0f;

    loadA(0);
    loadB(0, sb);
    storeA(0);
    CP_WAIT0();
    __syncthreads();

    for (int c = 0; c < NCHUNK_AT; c++) {
        const uint32_t stoff = (uint32_t)((c & 1) * AT_STAGE);
        const uint32_t nxoff = (uint32_t)(((c + 1) & 1) * AT_STAGE);
        const bool more = (c + 1 < NCHUNK_AT);
        if (more) { loadA((c + 1) * BKC); loadB((c + 1) * BKC, sb + nxoff); }

#pragma unroll
        for (int kk = 0; kk < 2; kk++) {
            const uint32_t kb = kk * 32;
            uint32_t ah[2][4], al[2][4], bh[4][4], bl[4][4];
#pragma unroll
            for (int mi = 0; mi < 2; mi++)
                ldsm4(ah[mi], sb + stoff + a_lane_off + mi * (16 * AT_ROWB) + kb);
#pragma unroll
            for (int nj = 0; nj < 4; nj++) {
                ldsm4(bh[nj], sb + stoff + AT_BHI + b_lane_off + nj * (16 * AT_ROWB) + kb);
                ldsm4(bl[nj], sb + stoff + AT_BLO + b_lane_off + nj * (16 * AT_ROWB) + kb);
            }
#pragma unroll
            for (int mi = 0; mi < 2; mi++)
#pragma unroll
                for (int nf = 0; nf < 8; nf++)
                    mma_bf16(acc[mi][nf], ah[mi], bh[nf >> 1][(nf & 1) * 2], bh[nf >> 1][(nf & 1) * 2 + 1]);
#pragma unroll
            for (int mi = 0; mi < 2; mi++)
#pragma unroll
                for (int nf = 0; nf < 8; nf++)
                    mma_bf16(acc[mi][nf], ah[mi], bl[nf >> 1][(nf & 1) * 2], bl[nf >> 1][(nf & 1) * 2 + 1]);
#pragma unroll
            for (int mi = 0; mi < 2; mi++)
                ldsm4(al[mi], sb + stoff + AT_ALO + a_lane_off + mi * (16 * AT_ROWB) + kb);
#pragma unroll
            for (int mi = 0; mi < 2; mi++)
#pragma unroll
                for (int nf = 0; nf < 8; nf++)
                    mma_bf16(acc[mi][nf], al[mi], bh[nf >> 1][(nf & 1) * 2], bh[nf >> 1][(nf & 1) * 2 + 1]);
        }

        if (more) storeA(nxoff);
        CP_WAIT0();
        __syncthreads();
    }

    // epilogue: write RAW acc into simT (overlays dead stage buffers)
    float* simT = (float*)smem;
    const int gid = lane >> 2, tig = lane & 3;
#pragma unroll
    for (int mi = 0; mi < 2; mi++) {
        const int r = wm * 32 + mi * 16 + gid;
#pragma unroll
        for (int nf = 0; nf < 8; nf++) {
            const int cb = wn * 64 + nf * 8 + tig * 2;
            simT[r * SIMW + cb]           = acc[mi][nf][0];
            simT[r * SIMW + cb + 1]       = acc[mi][nf][1];
            simT[(r + 8) * SIMW + cb]     = acc[mi][nf][2];
            simT[(r + 8) * SIMW + cb + 1] = acc[mi][nf][3];
        }
    }
    __syncthreads();

    // softmax + label bucketing; col 127 holds dq_i = x_i.u
    if (tid < NV) {
        const int r = tid;
        const float dqbb = simT[r * SIMW + 127] + g_bb[0];
        float m = -1e30f;
#pragma unroll 4
        for (int ss = 0; ss < SPE; ss++) {
            float v = (simT[r * SIMW + ss] + dqbb + dscol[ss]) * invn[ss];
            m = fmaxf(m, v);
        }
        float* p = probsS[r];
#pragma unroll
        for (int c = 0; c < NCLS; c++) p[c] = 0.0f;
        float sum = 0.0f;
        for (int ss = 0; ss < SPE; ss++) {
            float v = (simT[r * SIMW + ss] + dqbb + dscol[ss]) * invn[ss];
            float w = expf(v - m);
            sum += w;
            p[lab[ss]] += w;
        }
        const float invsum = 1.0f / sum;
        const int grow = qbase + r;
        int bestc = 0;
        float bestv = p[0];
#pragma unroll
        for (int c = 0; c < NCLS; c++) {
            float v = p[c] * invsum;
            out[(size_t)grow * NCLS + c] = v;
            if (p[c] > bestv) { bestv = p[c]; bestc = c; }
        }
        if (out_size >= NQRY * NCLS + NQRY)
            out[NQRY * NCLS + grow] = (float)bestc;
    }
}

// ---------------------------------------------------------------------------
extern "C" void kernel_launch(void* const* d_in, const int* in_sizes, int n_in,
                              void* d_out, int out_size) {
    const float* support = (const float*)d_in[0];
    const float* query   = (const float*)d_in[1];
    const float* onehot  = (const float*)d_in[2];
    const float* W       = (const float*)d_in[3];
    const float* b       = (const float*)d_in[4];
    float* out = (float*)d_out;

    __nv_bfloat16 *whi, *wlo, *xhi, *xlo, *mhi, *mlo, *zhi, *zlo;
    float* mp;
    cudaGetSymbolAddress((void**)&whi, g_w_hi);
    cudaGetSymbolAddress((void**)&wlo, g_w_lo);
    cudaGetSymbolAddress((void**)&xhi, g_xs_hi);
    cudaGetSymbolAddress((void**)&xlo, g_xs_lo);
    cudaGetSymbolAddress((void**)&mhi, g_m_hi);
    cudaGetSymbolAddress((void**)&mlo, g_m_lo);
    cudaGetSymbolAddress((void**)&zhi, g_z_hi);
    cudaGetSymbolAddress((void**)&zlo, g_z_lo);
    cudaGetSymbolAddress((void**)&mp, g_mp);

    cudaFuncSetAttribute((const void*)gemm_split<true>,
                         cudaFuncAttributeMaxDynamicSharedMemorySize, GEMM_SMEM);
    cudaFuncSetAttribute((const void*)gemm_split<false>,
                         cudaFuncAttributeMaxDynamicSharedMemorySize, GEMM_SMEM);
    cudaFuncSetAttribute((const void*)attention_mma,
                         cudaFuncAttributeMaxDynamicSharedMemorySize, AT_SMEM);

    // 1. split W and support into bf16 hi/lo
    split_arr<<<(GK * GK) / 1024, 256>>>(W, whi, wlo);
    split_arr<<<(NSUP * GK) / 1024, 256>>>(support, xhi, xlo);
    // 2. bias terms: u = W b (fp32 + split), bb = b.b
    wb_kernel<<<GK, 256>>>(W, b);
    bb_kernel<<<1, 256>>>(b);
    // 3. M = W W^T, lower triangle, split-K (272 CTAs, 2/SM, one wave)
    gemm_split<true><<<272, 256, GEMM_SMEM>>>(whi, wlo, whi, wlo, nullptr, nullptr, mp);
    // 4. combine partials + split + fused mirror
    combine_m<<<dim3(136, 16), 256>>>();
    // 5. Z = Xs M (presplit A via cp.async path)
    gemm_split<false><<<dim3(16, NSUP / 128), 256, GEMM_SMEM>>>(
        xhi, xlo, mhi, mlo, zhi, zlo, nullptr);
    // 6. support norms + d_j (query dots folded into attention via u-rows)
    znorm_kernel<<<NSUP, 256>>>(support);
    // 7. fused attention sim/softmax/classify (R12 config)
    attention_mma<<<dim3(2, NEP), 320, AT_SMEM>>>(query, onehot, out, out_size);
}

// round 17
// speedup vs baseline: 1.0247x; 1.0101x over previous
#include <cuda_runtime.h>
#include <cuda_bf16.h>
#include <math.h>
#include <stdint.h>

// Problem constants: B=64, C=20, K=5, Q=15, D=H=2048
#define D_DIM 2048
#define GK    2048
#define NSUP  6400
#define NQRY  19200
#define NEP   64
#define SPE   100
#define QPE   300
#define NCLS  20

// Scratch (device globals: allocation-free per harness rules)
__device__ __nv_bfloat16 g_w_hi[GK * GK];     // W split hi  [k][n]
__device__ __nv_bfloat16 g_w_lo[GK * GK];
__device__ __nv_bfloat16 g_m_hi[GK * GK];     // M = W W^T split hi [i][j]
__device__ __nv_bfloat16 g_m_lo[GK * GK];
__device__ __nv_bfloat16 g_z_hi[NSUP * GK];   // Z = Xs M split hi [s][k]
__device__ __nv_bfloat16 g_z_lo[NSUP * GK];
__device__ float g_u[GK];                      // u = W b (fp32)
__device__ __nv_bfloat16 g_u_hi[GK];           // u split hi
__device__ __nv_bfloat16 g_u_lo[GK];           // u split lo
__device__ float g_bb[1];                      // b.b
__device__ float g_ds[NSUP];                   // d_j = x_j . u
__device__ float g_inv[NSUP];                  // inv support norms

// ---------------------------------------------------------------------------
// PTX helpers (plain sm_80+ only — legal at compute_103 non-'a')
// ---------------------------------------------------------------------------
__device__ __forceinline__ uint32_t smem_u32(const void* p) {
    uint32_t a;
    asm("{ .reg .u64 t; cvta.to.shared.u64 t, %1; cvt.u32.u64 %0, t; }" : "=r"(a) : "l"(p));
    return a;
}
__device__ __forceinline__ void ldsm4(uint32_t* r, uint32_t addr) {
    asm volatile("ldmatrix.sync.aligned.m8n8.x4.shared.b16 {%0,%1,%2,%3}, [%4];"
                 : "=r"(r[0]), "=r"(r[1]), "=r"(r[2]), "=r"(r[3]) : "r"(addr));
}
__device__ __forceinline__ void mma_bf16(float* d, const uint32_t* a, uint32_t b0, uint32_t b1) {
    asm volatile("mma.sync.aligned.m16n8k16.row.col.f32.bf16.bf16.f32 "
                 "{%0,%1,%2,%3}, {%4,%5,%6,%7}, {%8,%9}, {%0,%1,%2,%3};"
                 : "+f"(d[0]), "+f"(d[1]), "+f"(d[2]), "+f"(d[3])
                 : "r"(a[0]), "r"(a[1]), "r"(a[2]), "r"(a[3]), "r"(b0), "r"(b1));
}
__device__ __forceinline__ void cp_async16(uint32_t dst, const void* src) {
    asm volatile("cp.async.ca.shared.global [%0], [%1], 16;" :: "r"(dst), "l"(src));
}
#define CP_COMMIT() asm volatile("cp.async.commit_group;" ::: "memory")
#define CP_WAIT0()  asm volatile("cp.async.wait_group 0;"  ::: "memory")

__device__ __forceinline__ void split2(float x, float y, uint32_t& h, uint32_t& l) {
    __nv_bfloat162 hh = __floats2bfloat162_rn(x, y);
    __nv_bfloat162 ll = __floats2bfloat162_rn(x - __low2float(hh), y - __high2float(hh));
    h = *reinterpret_cast<uint32_t*>(&hh);
    l = *reinterpret_cast<uint32_t*>(&ll);
}

// ---------------------------------------------------------------------------
// Fused W prep: one pass over W row r -> split to g_w_hi/lo AND u[r] = W[r].b.
// Block 0 additionally computes bb = b.b. Grid = GK rows, 256 threads.
// ---------------------------------------------------------------------------
__global__ __launch_bounds__(256)
void wprep(const float* __restrict__ W, const float* __restrict__ b) {
    const int row = blockIdx.x;
    const float* p = W + (size_t)row * GK;
    float sum = 0.0f;
    for (int k = threadIdx.x * 8; k < GK; k += 2048) {
        float4 v0 = *(const float4*)(p + k);
        float4 v1 = *(const float4*)(p + k + 4);
        float4 b0 = *(const float4*)(b + k);
        float4 b1 = *(const float4*)(b + k + 4);
        uint32_t h0, l0, h1, l1, h2, l2, h3, l3;
        split2(v0.x, v0.y, h0, l0);
        split2(v0.z, v0.w, h1, l1);
        split2(v1.x, v1.y, h2, l2);
        split2(v1.z, v1.w, h3, l3);
        *(uint4*)(g_w_hi + (size_t)row * GK + k) = make_uint4(h0, h1, h2, h3);
        *(uint4*)(g_w_lo + (size_t)row * GK + k) = make_uint4(l0, l1, l2, l3);
        sum = fmaf(v0.x, b0.x, sum); sum = fmaf(v0.y, b0.y, sum);
        sum = fmaf(v0.z, b0.z, sum); sum = fmaf(v0.w, b0.w, sum);
        sum = fmaf(v1.x, b1.x, sum); sum = fmaf(v1.y, b1.y, sum);
        sum = fmaf(v1.z, b1.z, sum); sum = fmaf(v1.w, b1.w, sum);
    }
#pragma unroll
    for (int o = 16; o > 0; o >>= 1) sum += __shfl_down_sync(0xFFFFFFFF, sum, o);
    __shared__ float ws[8];
    if ((threadIdx.x & 31) == 0) ws[threadIdx.x >> 5] = sum;
    __syncthreads();
    if (threadIdx.x == 0) {
        float t = 0.0f;
#pragma unroll
        for (int w = 0; w < 8; w++) t += ws[w];
        g_u[row] = t;
        __nv_bfloat16 h = __float2bfloat16_rn(t);
        g_u_hi[row] = h;
        g_u_lo[row] = __float2bfloat16_rn(t - __bfloat162float(h));
    }
    // block 0: bb = b.b
    if (blockIdx.x == 0) {
        float s = 0.0f;
        for (int k = threadIdx.x; k < GK; k += 256) { float v = b[k]; s = fmaf(v, v, s); }
#pragma unroll
        for (int o = 16; o > 0; o >>= 1) s += __shfl_down_sync(0xFFFFFFFF, s, o);
        __shared__ float ws2[8];
        if ((threadIdx.x & 31) == 0) ws2[threadIdx.x >> 5] = s;
        __syncthreads();
        if (threadIdx.x == 0) {
            float t = 0.0f;
#pragma unroll
            for (int w = 0; w < 8; w++) t += ws2[w];
            g_bb[0] = t;
        }
    }
}

// ---------------------------------------------------------------------------
// Support norms: |s_j|^2 = x_j.z_j + 2 x_j.u + bb ; also store d_j = x_j.u
// ---------------------------------------------------------------------------
__global__ void znorm_kernel(const float* __restrict__ Xs) {
    const int row = blockIdx.x;
    const float* x = Xs + (size_t)row * GK;
    const __nv_bfloat16* zh = g_z_hi + (size_t)row * GK;
    const __nv_bfloat16* zl = g_z_lo + (size_t)row * GK;
    float s1 = 0.0f, s2 = 0.0f;
    for (int k = threadIdx.x * 4; k < GK; k += 1024) {
        float4 x4 = *(const float4*)(x + k);
        float4 u4 = *(const float4*)(g_u + k);
        uint2 zh2 = *(const uint2*)(zh + k);
        uint2 zl2 = *(const uint2*)(zl + k);
        __nv_bfloat162 h0 = *(__nv_bfloat162*)&zh2.x, h1 = *(__nv_bfloat162*)&zh2.y;
        __nv_bfloat162 l0 = *(__nv_bfloat162*)&zl2.x, l1 = *(__nv_bfloat162*)&zl2.y;
        s1 = fmaf(__low2float(h0) + __low2float(l0), x4.x, s1);
        s1 = fmaf(__high2float(h0) + __high2float(l0), x4.y, s1);
        s1 = fmaf(__low2float(h1) + __low2float(l1), x4.z, s1);
        s1 = fmaf(__high2float(h1) + __high2float(l1), x4.w, s1);
        s2 = fmaf(x4.x, u4.x, s2); s2 = fmaf(x4.y, u4.y, s2);
        s2 = fmaf(x4.z, u4.z, s2); s2 = fmaf(x4.w, u4.w, s2);
    }
#pragma unroll
    for (int o = 16; o > 0; o >>= 1) {
        s1 += __shfl_down_sync(0xFFFFFFFF, s1, o);
        s2 += __shfl_down_sync(0xFFFFFFFF, s2, o);
    }
    __shared__ float w1[8], w2[8];
    if ((threadIdx.x & 31) == 0) { w1[threadIdx.x >> 5] = s1; w2[threadIdx.x >> 5] = s2; }
    __syncthreads();
    if (threadIdx.x == 0) {
        float t1 = 0.0f, t2 = 0.0f;
#pragma unroll
        for (int w = 0; w < 8; w++) { t1 += w1[w]; t2 += w2[w]; }
        float n2 = t1 + 2.0f * t2 + g_bb[0];
        g_inv[row] = rsqrtf(fmaxf(n2, 1e-10f));
        g_ds[row] = t2;
    }
}

// ---------------------------------------------------------------------------
// Split-bf16 GEMM (HMMA): O = A @ B^T. 3 terms, fp32 acc, split bf16 out.
// BM=128, BN=128, BK=32, 256 threads (8 warps 2x4, warp tile 64x32).
// TRI: FLAT 1-D triangular grid (136 CTAs, bx <= by) -> 1 CTA/SM.
// ---------------------------------------------------------------------------
#define BKC 32
#define NCHUNK (GK / BKC)
#define ROWB 80
#define OFF_AHI 0
#define OFF_ALO (128 * ROWB)
#define OFF_BHI (2 * 128 * ROWB)
#define OFF_BLO (3 * 128 * ROWB)
#define STAGEB  (4 * 128 * ROWB)          // 40960
#define GEMM_SMEM (2 * STAGEB)            // 81920

template <bool AFP32, bool TRI>
__global__ __launch_bounds__(256, 2)
void gemm_split(const float* __restrict__ Afp,
                const __nv_bfloat16* __restrict__ AhiG, const __nv_bfloat16* __restrict__ AloG,
                const __nv_bfloat16* __restrict__ Bhi, const __nv_bfloat16* __restrict__ Blo,
                __nv_bfloat16* __restrict__ Ohi, __nv_bfloat16* __restrict__ Olo) {
    int bx, by;
    if (TRI) {
        int i = blockIdx.x;
        int t = 0;
        while ((t + 1) * (t + 2) / 2 <= i) t++;
        by = t;
        bx = i - t * (t + 1) / 2;
    } else {
        bx = blockIdx.x; by = blockIdx.y;
    }
    extern __shared__ __align__(128) char smem[];
    const uint32_t sb = smem_u32(smem);
    const int tid = threadIdx.x;
    const int lane = tid & 31, warp = tid >> 5;
    const int wm = warp & 1, wn = warp >> 1;   // 2 x 4 warp grid, tile 64x32

    const float* Ab = AFP32 ? (Afp + (size_t)(by * 128) * GK) : nullptr;
    const __nv_bfloat16* AhiB = AFP32 ? nullptr : (AhiG + (size_t)(by * 128) * GK);
    const __nv_bfloat16* AloB = AFP32 ? nullptr : (AloG + (size_t)(by * 128) * GK);
    const size_t bn0 = (size_t)(bx * 128);

    float4 areg[4];
    auto loadA = [&](int k0) {
#pragma unroll
        for (int i = 0; i < 4; i++) {
            int task = tid + i * 256;
            areg[i] = *(const float4*)(Ab + (size_t)(task >> 3) * GK + k0 + (task & 7) * 4);
        }
    };
    auto storeA = [&](uint32_t stoff) {
#pragma unroll
        for (int i = 0; i < 4; i++) {
            int task = tid + i * 256;
            int row = task >> 3, c4 = task & 7;
            uint32_t h0, l0, h1, l1;
            split2(areg[i].x, areg[i].y, h0, l0);
            split2(areg[i].z, areg[i].w, h1, l1);
            *(uint2*)(smem + stoff + OFF_AHI + row * ROWB + c4 * 8) = make_uint2(h0, h1);
            *(uint2*)(smem + stoff + OFF_ALO + row * ROWB + c4 * 8) = make_uint2(l0, l1);
        }
    };
    auto cpA = [&](int k0, uint32_t stage) {
#pragma unroll
        for (int i = 0; i < 2; i++) {
            int task = tid + i * 256;
            int row = task >> 2, ch = task & 3;
            cp_async16(stage + OFF_AHI + row * ROWB + ch * 16, AhiB + (size_t)row * GK + k0 + ch * 8);
            cp_async16(stage + OFF_ALO + row * ROWB + ch * 16, AloB + (size_t)row * GK + k0 + ch * 8);
        }
    };
    auto loadB = [&](int k0, uint32_t stage) {
#pragma unroll
        for (int i = 0; i < 2; i++) {
            int task = tid + i * 256;
            int row = task >> 2, ch = task & 3;
            cp_async16(stage + OFF_BHI + row * ROWB + ch * 16, Bhi + (bn0 + row) * GK + k0 + ch * 8);
            cp_async16(stage + OFF_BLO + row * ROWB + ch * 16, Blo + (bn0 + row) * GK + k0 + ch * 8);
        }
        CP_COMMIT();
    };

    const uint32_t a_lane_off = (uint32_t)((wm * 64 + (lane & 15)) * ROWB + (lane >> 4) * 16);
    const uint32_t b_lane_off = (uint32_t)((wn * 32 + ((lane >> 4) << 3) + (lane & 7)) * ROWB
                                           + ((lane >> 3) & 1) * 16);

    float acc[4][4][4];
#pragma unroll
    for (int mi = 0; mi < 4; mi++)
#pragma unroll
        for (int ni = 0; ni < 4; ni++)
#pragma unroll
            for (int j = 0; j < 4; j++) acc[mi][ni][j] = 0.0f;

    if (AFP32) { loadA(0); } else { cpA(0, sb); }
    loadB(0, sb);
    if (AFP32) storeA(0);
    CP_WAIT0();
    __syncthreads();

    for (int c = 0; c < NCHUNK; c++) {
        const uint32_t stoff = (uint32_t)((c & 1) * STAGEB);
        const uint32_t nxoff = (uint32_t)(((c + 1) & 1) * STAGEB);
        const bool more = (c + 1 < NCHUNK);
        if (more) {
            if (AFP32) loadA((c + 1) * BKC); else cpA((c + 1) * BKC, sb + nxoff);
            loadB((c + 1) * BKC, sb + nxoff);
        }

#pragma unroll
        for (int kk = 0; kk < 2; kk++) {
            const uint32_t kb = kk * 32;
            uint32_t ah[4][4], al[4][4], bh[2][4], bl[2][4];
#pragma unroll
            for (int mi = 0; mi < 4; mi++)
                ldsm4(ah[mi], sb + stoff + OFF_AHI + a_lane_off + mi * (16 * ROWB) + kb);
#pragma unroll
            for (int nj = 0; nj < 2; nj++) {
                ldsm4(bh[nj], sb + stoff + OFF_BHI + b_lane_off + nj * (16 * ROWB) + kb);
                ldsm4(bl[nj], sb + stoff + OFF_BLO + b_lane_off + nj * (16 * ROWB) + kb);
            }
#pragma unroll
            for (int mi = 0; mi < 4; mi++)
#pragma unroll
                for (int ni = 0; ni < 4; ni++)
                    mma_bf16(acc[mi][ni], ah[mi], bh[ni >> 1][(ni & 1) * 2], bh[ni >> 1][(ni & 1) * 2 + 1]);
#pragma unroll
            for (int mi = 0; mi < 4; mi++)
#pragma unroll
                for (int ni = 0; ni < 4; ni++)
                    mma_bf16(acc[mi][ni], ah[mi], bl[ni >> 1][(ni & 1) * 2], bl[ni >> 1][(ni & 1) * 2 + 1]);
#pragma unroll
            for (int mi = 0; mi < 4; mi++)
                ldsm4(al[mi], sb + stoff + OFF_ALO + a_lane_off + mi * (16 * ROWB) + kb);
#pragma unroll
            for (int mi = 0; mi < 4; mi++)
#pragma unroll
                for (int ni = 0; ni < 4; ni++)
                    mma_bf16(acc[mi][ni], al[mi], bh[ni >> 1][(ni & 1) * 2], bh[ni >> 1][(ni & 1) * 2 + 1]);
        }

        if (more && AFP32) storeA(nxoff);
        CP_WAIT0();
        __syncthreads();
    }

    const int gid = lane >> 2, tig = lane & 3;
#pragma unroll
    for (int mi = 0; mi < 4; mi++) {
        const int r0 = by * 128 + wm * 64 + mi * 16 + gid;
#pragma unroll
        for (int ni = 0; ni < 4; ni++) {
            const int col = bx * 128 + wn * 32 + ni * 8 + tig * 2;
            uint32_t h, l;
            split2(acc[mi][ni][0], acc[mi][ni][1], h, l);
            *(uint32_t*)(Ohi + (size_t)r0 * GK + col) = h;
            *(uint32_t*)(Olo + (size_t)r0 * GK + col) = l;
            split2(acc[mi][ni][2], acc[mi][ni][3], h, l);
            *(uint32_t*)(Ohi + (size_t)(r0 + 8) * GK + col) = h;
            *(uint32_t*)(Olo + (size_t)(r0 + 8) * GK + col) = l;
        }
    }
}

// ---------------------------------------------------------------------------
// Mirror M's upper triangle from computed lower triangle (smem transpose).
// FLAT triangular grid: 2080 = 64*65/2 CTAs (32x32 subtiles, b >= a).
// ---------------------------------------------------------------------------
__global__ __launch_bounds__(256)
void mirror_m() {
    int i = blockIdx.x;
    int t = 0;
    while ((t + 1) * (t + 2) / 2 <= i) t++;
    const int bxi = t, byi = i - t * (t + 1) / 2;   // bxi >= byi
    const int a = byi * 32, b = bxi * 32;
    __shared__ __nv_bfloat16 th[32][33], tl[32][33];
    const int tx = threadIdx.x & 31, ty = threadIdx.x >> 5;
#pragma unroll
    for (int i2 = 0; i2 < 4; i2++) {
        int r = ty + i2 * 8;
        th[r][tx] = g_m_hi[(size_t)(b + r) * GK + a + tx];
        tl[r][tx] = g_m_lo[(size_t)(b + r) * GK + a + tx];
    }
    __syncthreads();
    const bool diag = (bxi == byi);
#pragma unroll
    for (int i2 = 0; i2 < 4; i2++) {
        int r = ty + i2 * 8;
        int row = a + r, col = b + tx;
        if (!diag || col > row) {
            g_m_hi[(size_t)row * GK + col] = th[tx][r];
            g_m_lo[(size_t)row * GK + col] = tl[tx][r];
        }
    }
}

// ---------------------------------------------------------------------------
// Fused attention via HMMA (R12 config): grid (2, 64); 160 query rows (150
// valid) x 128 support cols. B pad rows 100..127 hold u -> acc col 127 is
// dq_i = x_i.u. 320 threads = 10 warps (5m x 2n), warp tile 32x64. simT
// overlays the dead stage buffers.
// ---------------------------------------------------------------------------
#define NV 150
#define AT_ROWB 80
#define AT_AHI 0
#define AT_ALO (160 * AT_ROWB)
#define AT_BHI (2 * 160 * AT_ROWB)
#define AT_BLO (AT_BHI + 128 * AT_ROWB)
#define AT_STAGE (AT_BLO + 128 * AT_ROWB)      // 46080
#define SIMW 132
#define AT_SMEM (2 * AT_STAGE)                 // 92160 (simT overlays stages)

__global__ __launch_bounds__(320, 1)
void attention_mma(const float* __restrict__ query, const float* __restrict__ onehot,
                   float* __restrict__ out, int out_size) {
    extern __shared__ __align__(128) char smem[];
    __shared__ float invn[SPE], dscol[SPE];
    __shared__ int lab[SPE];
    __shared__ float probsS[160][NCLS];
    const uint32_t sb = smem_u32(smem);
    const int tid = threadIdx.x, lane = tid & 31, warp = tid >> 5;
    const int wm = warp >> 1, wn = warp & 1;   // 5 x 2
    const int t = blockIdx.x, e = blockIdx.y;
    const int qbase = e * QPE + t * NV;
    const int sbase = e * SPE;

    if (tid < SPE) {
        invn[tid] = g_inv[sbase + tid];
        dscol[tid] = g_ds[sbase + tid];
        const float* oh = onehot + (size_t)(e * SPE + tid) * NCLS;
        int l = 0;
        float best = oh[0];
#pragma unroll
        for (int c = 1; c < NCLS; c++) { float v = oh[c]; if (v > best) { best = v; l = c; } }
        lab[tid] = l;
    }

    float4 areg[4];
    auto loadA = [&](int k0) {
#pragma unroll
        for (int i = 0; i < 4; i++) {
            int task = tid + i * 320;       // 1280 tasks = 160 rows x 8 chunks
            int row = task >> 3, c4 = task & 7;
            int qr = qbase + min(row, NV - 1);
            areg[i] = *(const float4*)(query + (size_t)qr * GK + k0 + c4 * 4);
        }
    };
    auto storeA = [&](uint32_t stoff) {
#pragma unroll
        for (int i = 0; i < 4; i++) {
            int task = tid + i * 320;
            int row = task >> 3, c4 = task & 7;
            uint32_t h0, l0, h1, l1;
            split2(areg[i].x, areg[i].y, h0, l0);
            split2(areg[i].z, areg[i].w, h1, l1);
            *(uint2*)(smem + stoff + AT_AHI + row * AT_ROWB + c4 * 8) = make_uint2(h0, h1);
            *(uint2*)(smem + stoff + AT_ALO + row * AT_ROWB + c4 * 8) = make_uint2(l0, l1);
        }
    };
    auto loadB = [&](int k0, uint32_t stage) {
        for (int idx = tid; idx < 512; idx += 320) {   // 128 rows x 4 chunks
            int row = idx >> 2, ch = idx & 3;
            const __nv_bfloat16* srch;
            const __nv_bfloat16* srcl;
            if (row < SPE) {
                srch = g_z_hi + (size_t)(sbase + row) * GK + k0 + ch * 8;
                srcl = g_z_lo + (size_t)(sbase + row) * GK + k0 + ch * 8;
            } else {   // padding rows carry u -> acc col = x.u (dq)
                srch = g_u_hi + k0 + ch * 8;
                srcl = g_u_lo + k0 + ch * 8;
            }
            cp_async16(stage + AT_BHI + row * AT_ROWB + ch * 16, srch);
            cp_async16(stage + AT_BLO + row * AT_ROWB + ch * 16, srcl);
        }
        CP_COMMIT();
    };

    const uint32_t a_lane_off = (uint32_t)((wm * 32 + (lane & 15)) * AT_ROWB + (lane >> 4) * 16);
    const uint32_t b_lane_off = (uint32_t)((wn * 64 + ((lane >> 4) << 3) + (lane & 7)) * AT_ROWB
                                           + ((lane >> 3) & 1) * 16);

    float acc[2][8][4];
#pragma unroll
    for (int mi = 0; mi < 2; mi++)
#pragma unroll
        for (int nf = 0; nf < 8; nf++)
#pragma unroll
            for (int j = 0; j < 4; j++) acc[mi][nf][j] = 0.0f;

    loadA(0);
    loadB(0, sb);
    storeA(0);
    CP_WAIT0();
    __syncthreads();

    for (int c = 0; c < NCHUNK; c++) {
        const uint32_t stoff = (uint32_t)((c & 1) * AT_STAGE);
        const uint32_t nxoff = (uint32_t)(((c + 1) & 1) * AT_STAGE);
        const bool more = (c + 1 < NCHUNK);
        if (more) { loadA((c + 1) * BKC); loadB((c + 1) * BKC, sb + nxoff); }

#pragma unroll
        for (int kk = 0; kk < 2; kk++) {
            const uint32_t kb = kk * 32;
            uint32_t ah[2][4], al[2][4], bh[4][4], bl[4][4];
#pragma unroll
            for (int mi = 0; mi < 2; mi++)
                ldsm4(ah[mi], sb + stoff + AT_AHI + a_lane_off + mi * (16 * AT_ROWB) + kb);
#pragma unroll
            for (int nj = 0; nj < 4; nj++) {
                ldsm4(bh[nj], sb + stoff + AT_BHI + b_lane_off + nj * (16 * AT_ROWB) + kb);
                ldsm4(bl[nj], sb + stoff + AT_BLO + b_lane_off + nj * (16 * AT_ROWB) + kb);
            }
#pragma unroll
            for (int mi = 0; mi < 2; mi++)
#pragma unroll
                for (int nf = 0; nf < 8; nf++)
                    mma_bf16(acc[mi][nf], ah[mi], bh[nf >> 1][(nf & 1) * 2], bh[nf >> 1][(nf & 1) * 2 + 1]);
#pragma unroll
            for (int mi = 0; mi < 2; mi++)
#pragma unroll
                for (int nf = 0; nf < 8; nf++)
                    mma_bf16(acc[mi][nf], ah[mi], bl[nf >> 1][(nf & 1) * 2], bl[nf >> 1][(nf & 1) * 2 + 1]);
#pragma unroll
            for (int mi = 0; mi < 2; mi++)
                ldsm4(al[mi], sb + stoff + AT_ALO + a_lane_off + mi * (16 * AT_ROWB) + kb);
#pragma unroll
            for (int mi = 0; mi < 2; mi++)
#pragma unroll
                for (int nf = 0; nf < 8; nf++)
                    mma_bf16(acc[mi][nf], al[mi], bh[nf >> 1][(nf & 1) * 2], bh[nf >> 1][(nf & 1) * 2 + 1]);
        }

        if (more) storeA(nxoff);
        CP_WAIT0();
        __syncthreads();
    }

    // epilogue: write RAW acc into simT (overlays dead stage buffers)
    float* simT = (float*)smem;
    const int gid = lane >> 2, tig = lane & 3;
#pragma unroll
    for (int mi = 0; mi < 2; mi++) {
        const int r = wm * 32 + mi * 16 + gid;
#pragma unroll
        for (int nf = 0; nf < 8; nf++) {
            const int cb = wn * 64 + nf * 8 + tig * 2;
            simT[r * SIMW + cb]           = acc[mi][nf][0];
            simT[r * SIMW + cb + 1]       = acc[mi][nf][1];
            simT[(r + 8) * SIMW + cb]     = acc[mi][nf][2];
            simT[(r + 8) * SIMW + cb + 1] = acc[mi][nf][3];
        }
    }
    __syncthreads();

    // softmax + label bucketing; col 127 holds dq_i = x_i.u
    if (tid < NV) {
        const int r = tid;
        const float dqbb = simT[r * SIMW + 127] + g_bb[0];
        float m = -1e30f;
#pragma unroll 4
        for (int ss = 0; ss < SPE; ss++) {
            float v = (simT[r * SIMW + ss] + dqbb + dscol[ss]) * invn[ss];
            m = fmaxf(m, v);
        }
        float* p = probsS[r];
#pragma unroll
        for (int c = 0; c < NCLS; c++) p[c] = 0.0f;
        float sum = 0.0f;
        for (int ss = 0; ss < SPE; ss++) {
            float v = (simT[r * SIMW + ss] + dqbb + dscol[ss]) * invn[ss];
            float w = expf(v - m);
            sum += w;
            p[lab[ss]] += w;
        }
        const float invsum = 1.0f / sum;
        const int grow = qbase + r;
        int bestc = 0;
        float bestv = p[0];
#pragma unroll
        for (int c = 0; c < NCLS; c++) {
            float v = p[c] * invsum;
            out[(size_t)grow * NCLS + c] = v;
            if (p[c] > bestv) { bestv = p[c]; bestc = c; }
        }
        if (out_size >= NQRY * NCLS + NQRY)
            out[NQRY * NCLS + grow] = (float)bestc;
    }
}

// ---------------------------------------------------------------------------
extern "C" void kernel_launch(void* const* d_in, const int* in_sizes, int n_in,
                              void* d_out, int out_size) {
    const float* support = (const float*)d_in[0];
    const float* query   = (const float*)d_in[1];
    const float* onehot  = (const float*)d_in[2];
    const float* W       = (const float*)d_in[3];
    const float* b       = (const float*)d_in[4];
    float* out = (float*)d_out;

    __nv_bfloat16 *whi, *wlo, *mhi, *mlo, *zhi, *zlo;
    cudaGetSymbolAddress((void**)&whi, g_w_hi);
    cudaGetSymbolAddress((void**)&wlo, g_w_lo);
    cudaGetSymbolAddress((void**)&mhi, g_m_hi);
    cudaGetSymbolAddress((void**)&mlo, g_m_lo);
    cudaGetSymbolAddress((void**)&zhi, g_z_hi);
    cudaGetSymbolAddress((void**)&zlo, g_z_lo);

    cudaFuncSetAttribute((const void*)gemm_split<false, true>,
                         cudaFuncAttributeMaxDynamicSharedMemorySize, GEMM_SMEM);
    cudaFuncSetAttribute((const void*)gemm_split<true, false>,
                         cudaFuncAttributeMaxDynamicSharedMemorySize, GEMM_SMEM);
    cudaFuncSetAttribute((const void*)attention_mma,
                         cudaFuncAttributeMaxDynamicSharedMemorySize, AT_SMEM);

    // 1. fused W prep: split W + u = W b + bb (one pass over W)
    wprep<<<GK, 256>>>(W, b);
    // 2. M = W W^T, lower triangle on a FLAT 136-CTA grid, then mirror (flat)
    gemm_split<false, true><<<136, 256, GEMM_SMEM>>>(
        nullptr, whi, wlo, whi, wlo, mhi, mlo);
    mirror_m<<<2080, 256>>>();
    // 3. Z = Xs M
    gemm_split<true, false><<<dim3(16, NSUP / 128), 256, GEMM_SMEM>>>(
        support, nullptr, nullptr, mhi, mlo, zhi, zlo);
    // 4. support norms + d_j (query dots folded into attention via u-rows)
    znorm_kernel<<<NSUP, 256>>>(support);
    // 5. fused attention sim/softmax/classify (R12 config)
    attention_mma<<<dim3(2, NEP), 320, AT_SMEM>>>(query, onehot, out, out_size);
}